// round 3
// baseline (speedup 1.0000x reference)
#include <cuda_runtime.h>
#include <cstddef>

namespace {

constexpr int B = 8, T = 2048, H = 256, L = 16;
constexpr int S = 32;                  // t-strip length per block
constexpr int WARPS = 8;               // warp g owns l in {2g, 2g+1}
constexpr int THREADS = WARPS * 32;    // 256
constexpr int STRIPS_PER_B = T / S;    // 64
constexpr int NBLOCKS = B * STRIPS_PER_B;  // 512

struct R8 { float v[8]; };

// Load 8 consecutive floats of row `row` (this lane's H-slice); zeros when OOB
// (implements the reference's zero padding on both ends).
__device__ __forceinline__ R8 load_row8(const float* __restrict__ base, int row, int hbase) {
  R8 r;
  if ((unsigned)row < (unsigned)T) {
    const float4* p = reinterpret_cast<const float4*>(base + (size_t)row * H + hbase);
    float4 a = p[0];
    float4 b = p[1];
    r.v[0] = a.x; r.v[1] = a.y; r.v[2] = a.z; r.v[3] = a.w;
    r.v[4] = b.x; r.v[5] = b.y; r.v[6] = b.z; r.v[7] = b.w;
  } else {
#pragma unroll
    for (int j = 0; j < 8; j++) r.v[j] = 0.f;
  }
  return r;
}

__device__ __forceinline__ unsigned long long pack2(float a, float b) {
  unsigned long long r;
  asm("mov.b64 %0, {%1, %2};" : "=l"(r) : "f"(a), "f"(b));
  return r;
}
__device__ __forceinline__ void unpack2(unsigned long long p, float& a, float& b) {
  asm("mov.b64 {%0, %1}, %2;" : "=f"(a), "=f"(b) : "l"(p));
}
__device__ __forceinline__ unsigned long long addx2(unsigned long long a, unsigned long long b) {
  unsigned long long r;
  asm("add.rn.f32x2 %0, %1, %2;" : "=l"(r) : "l"(a), "l"(b));
  return r;
}

__global__ __launch_bounds__(THREADS)
void ffm_kernel(const float* __restrict__ logits,
                const float* __restrict__ end_w,
                const float* __restrict__ whole_w,
                const float* __restrict__ relay_w,
                const float* __restrict__ relay_b,
                const float* __restrict__ length_bias,
                float* __restrict__ out,
                float* __restrict__ relay_out) {
  const int strip = blockIdx.x;
  const int b     = strip / STRIPS_PER_B;
  const int s0    = (strip % STRIPS_PER_B) * S;
  const int g     = threadIdx.x >> 5;   // warp id: l in {2g, 2g+1}
  const int lane  = threadIdx.x & 31;
  const int hbase = lane * 8;

  // Weights in registers for the whole strip (vectorized loads).
  float w0[8], w1[8], ew[8], rw[8];
#pragma unroll
  for (int q = 0; q < 2; q++) {
    float4 a = *reinterpret_cast<const float4*>(whole_w + (2 * g + 0) * H + hbase + 4 * q);
    float4 c = *reinterpret_cast<const float4*>(whole_w + (2 * g + 1) * H + hbase + 4 * q);
    float4 ee = *reinterpret_cast<const float4*>(end_w + hbase + 4 * q);
    w0[4 * q + 0] = a.x; w0[4 * q + 1] = a.y; w0[4 * q + 2] = a.z; w0[4 * q + 3] = a.w;
    w1[4 * q + 0] = c.x; w1[4 * q + 1] = c.y; w1[4 * q + 2] = c.z; w1[4 * q + 3] = c.w;
    ew[4 * q + 0] = ee.x; ew[4 * q + 1] = ee.y; ew[4 * q + 2] = ee.z; ew[4 * q + 3] = ee.w;
  }
  if (g == 0) {
#pragma unroll
    for (int q = 0; q < 2; q++) {
      float4 rr = *reinterpret_cast<const float4*>(relay_w + hbase + 4 * q);
      rw[4 * q + 0] = rr.x; rw[4 * q + 1] = rr.y; rw[4 * q + 2] = rr.z; rw[4 * q + 3] = rr.w;
    }
  }
  const float2 bias = *reinterpret_cast<const float2*>(length_bias + 2 * g);
  const float rb = relay_b[0];

  const float* lb = logits + (size_t)b * T * H;

  // 2-row register window. At step u (p = u & 1): slot p holds row r-2g,
  // slot p^1 holds row r-2g-1 (loaded in the previous step).
  R8 Wn[2];
  Wn[1] = load_row8(lb, s0 - 2 * g - 1, hbase);   // prefill for u = -1

  for (int u0 = 0; u0 < S; u0 += 2) {
#pragma unroll
    for (int p = 0; p < 2; p++) {
      const int r = s0 + u0 + p;

      Wn[p] = load_row8(lb, r - 2 * g, hbase);    // advance window
      R8 cur, nxt;
      if (g == 0) {
        cur = Wn[p];                              // warp 0: window row IS cur
        nxt = load_row8(lb, r + L, hbase);        // relay partner row
      } else {
        cur = load_row8(lb, r, hbase);
      }

      float e = 0.f, a0 = 0.f, a1 = 0.f, rel = 0.f;
#pragma unroll
      for (int j = 0; j < 8; j++) {
        const float c = cur.v[j];
        e  = fmaf(c, ew[j], e);
        a0 = fmaf(fmaxf(c, Wn[p].v[j]),     w0[j], a0);  // l = 2g
        a1 = fmaf(fmaxf(c, Wn[p ^ 1].v[j]), w1[j], a1);  // l = 2g+1
        if (g == 0) rel = fmaf(fmaxf(c, nxt.v[j]), rw[j], rel);
      }
      a0 += e; a1 += e;  // fold end-score partial (sum over lanes distributes)

      // Packed f32x2 butterfly reduction (both accs in one 64-bit chain).
      unsigned long long p01 = pack2(a0, a1);
#pragma unroll
      for (int s = 16; s > 0; s >>= 1)
        p01 = addx2(p01, __shfl_xor_sync(0xffffffffu, p01, s));

      if (g == 0) {
#pragma unroll
        for (int s = 16; s > 0; s >>= 1)
          rel += __shfl_xor_sync(0xffffffffu, rel, s);
        if (lane == 0) relay_out[(size_t)b * T + r] = rel + rb;
      }

      if (lane == 0) {
        float r0, r1;
        unpack2(p01, r0, r1);
        float2 o;
        o.x = r0 + bias.x;
        o.y = r1 + bias.y;
        *reinterpret_cast<float2*>(out + (size_t)(b * T + r) * L + 2 * g) = o;
      }
    }
  }
}

}  // namespace

extern "C" void kernel_launch(void* const* d_in, const int* in_sizes, int n_in,
                              void* d_out, int out_size) {
  const float* logits  = (const float*)d_in[0];
  const float* end_w   = (const float*)d_in[1];
  const float* whole_w = (const float*)d_in[2];
  const float* relay_w = (const float*)d_in[3];
  const float* relay_b = (const float*)d_in[4];
  const float* lbias   = (const float*)d_in[5];

  float* out   = (float*)d_out;                // [B, T, L]
  float* relay = out + (size_t)B * T * L;      // [B, T] appended

  ffm_kernel<<<NBLOCKS, THREADS>>>(logits, end_w, whole_w, relay_w, relay_b,
                                   lbias, out, relay);
}

// round 5
// speedup vs baseline: 3.3527x; 3.3527x over previous
#include <cuda_runtime.h>
#include <cstddef>

namespace {

constexpr int B = 8, T = 2048, H = 256, L = 16;
constexpr int S = 32;                  // t-strip per block
constexpr int WARPS = 4;               // warp g owns l in [4g, 4g+3]
constexpr int THREADS = WARPS * 32;    // 128
constexpr int STRIPS_PER_B = T / S;    // 64
constexpr int NBLOCKS = B * STRIPS_PER_B;  // 512

struct R8 { float v[8]; };
struct TrueT  { static constexpr bool value = true;  };
struct FalseT { static constexpr bool value = false; };

// Load 8 consecutive floats of row `row` (this lane's H-slice).
// CHK=true: zeros when row OOB (implements the reference's zero padding).
template <bool CHK>
__device__ __forceinline__ R8 load_row8(const float* __restrict__ base, int row, int hbase) {
  R8 r;
  if (!CHK || (unsigned)row < (unsigned)T) {
    const float4* p = reinterpret_cast<const float4*>(base + (size_t)row * H + hbase);
    float4 a = p[0];
    float4 b = p[1];
    r.v[0] = a.x; r.v[1] = a.y; r.v[2] = a.z; r.v[3] = a.w;
    r.v[4] = b.x; r.v[5] = b.y; r.v[6] = b.z; r.v[7] = b.w;
  } else {
#pragma unroll
    for (int j = 0; j < 8; j++) r.v[j] = 0.f;
  }
  return r;
}

// Interleaved merge: lanes with (lane&s)==0 end up carrying the a-class
// partial sum, lanes with (lane&s)!=0 the b-class. One shfl per merge.
__device__ __forceinline__ float shfl_merge(float a, float b, int s, int lane) {
  const bool hi = (lane & s) != 0;
  float send = hi ? a : b;            // what the partner needs
  float recv = __shfl_xor_sync(0xffffffffu, send, s);
  return (hi ? b : a) + recv;
}

__global__ __launch_bounds__(THREADS)
void ffm_kernel(const float* __restrict__ logits,
                const float* __restrict__ end_w,
                const float* __restrict__ whole_w,
                const float* __restrict__ relay_w,
                const float* __restrict__ relay_b,
                const float* __restrict__ length_bias,
                float* __restrict__ out,
                float* __restrict__ relay_out) {
  const int strip = blockIdx.x;
  const int b     = strip / STRIPS_PER_B;
  const int s0    = (strip % STRIPS_PER_B) * S;
  const int g     = threadIdx.x >> 5;   // warp id: l in [4g, 4g+3]
  const int lane  = threadIdx.x & 31;
  const int hbase = lane * 8;

  // Weights in registers for the whole strip.
  float w0[8], w1[8], w2[8], w3[8], ew[8], rw[8];
#pragma unroll
  for (int q = 0; q < 2; q++) {
    float4 x0 = *reinterpret_cast<const float4*>(whole_w + (4 * g + 0) * H + hbase + 4 * q);
    float4 x1 = *reinterpret_cast<const float4*>(whole_w + (4 * g + 1) * H + hbase + 4 * q);
    float4 x2 = *reinterpret_cast<const float4*>(whole_w + (4 * g + 2) * H + hbase + 4 * q);
    float4 x3 = *reinterpret_cast<const float4*>(whole_w + (4 * g + 3) * H + hbase + 4 * q);
    float4 xe = *reinterpret_cast<const float4*>(end_w + hbase + 4 * q);
    float4 xr = *reinterpret_cast<const float4*>(relay_w + hbase + 4 * q);
    w0[4*q+0]=x0.x; w0[4*q+1]=x0.y; w0[4*q+2]=x0.z; w0[4*q+3]=x0.w;
    w1[4*q+0]=x1.x; w1[4*q+1]=x1.y; w1[4*q+2]=x1.z; w1[4*q+3]=x1.w;
    w2[4*q+0]=x2.x; w2[4*q+1]=x2.y; w2[4*q+2]=x2.z; w2[4*q+3]=x2.w;
    w3[4*q+0]=x3.x; w3[4*q+1]=x3.y; w3[4*q+2]=x3.z; w3[4*q+3]=x3.w;
    ew[4*q+0]=xe.x; ew[4*q+1]=xe.y; ew[4*q+2]=xe.z; ew[4*q+3]=xe.w;
    rw[4*q+0]=xr.x; rw[4*q+1]=xr.y; rw[4*q+2]=xr.z; rw[4*q+3]=xr.w;
  }
  // Writer-lane mapping: lanes 0,16,8,24 hold finished sums for
  // l = 4g + idx with idx = ((lane>>4)&1) + ((lane>>3)&1)*2.
  const int  idx    = ((lane >> 4) & 1) + ((lane >> 3) & 1) * 2;
  const bool writer = (lane & 7) == 0;
  const float bias  = length_bias[4 * g + idx];
  const float rb    = relay_b[0];

  const float* lb = logits + (size_t)b * T * H;

  auto body = [&](auto chk_tag) {
    constexpr bool CHK = decltype(chk_tag)::value;

    // 4-row register window. Row (s0 + u - 4g) loaded at step u into slot u&3;
    // at step u (p = u & 3), row r-4g-k lives in slot (p - k) & 3.
    R8 Wn[4];
#pragma unroll
    for (int k = 1; k <= 3; k++)
      Wn[(4 - k) & 3] = load_row8<CHK>(lb, s0 - 4 * g - k, hbase);

    for (int u0 = 0; u0 < S; u0 += 4) {
#pragma unroll
      for (int p = 0; p < 4; p++) {
        const int r = s0 + u0 + p;

        Wn[p] = load_row8<CHK>(lb, r - 4 * g, hbase);  // advance window
        R8 cur, nxt;
        if (g == 0) {
          cur = Wn[p];                                 // warp 0: window row IS row r
          nxt = load_row8<CHK>(lb, r + L, hbase);      // relay partner row
        } else {
          cur = load_row8<false>(lb, r, hbase);        // row r always in-bounds
        }

        float e = 0.f, a0 = 0.f, a1 = 0.f, a2 = 0.f, a3 = 0.f;
#pragma unroll
        for (int j = 0; j < 8; j++) {
          const float c = cur.v[j];
          e  = fmaf(c, ew[j], e);
          a0 = fmaf(fmaxf(c, Wn[p].v[j]),           w0[j], a0);  // l = 4g
          a1 = fmaf(fmaxf(c, Wn[(p + 3) & 3].v[j]), w1[j], a1);  // l = 4g+1
          a2 = fmaf(fmaxf(c, Wn[(p + 2) & 3].v[j]), w2[j], a2);  // l = 4g+2
          a3 = fmaf(fmaxf(c, Wn[(p + 1) & 3].v[j]), w3[j], a3);  // l = 4g+3
        }
        // Fold end-score partial into each acc (lane-sum distributes).
        a0 += e; a1 += e; a2 += e; a3 += e;

        // Interleaved 4-value warp reduction: 5 shfl total.
        float x = shfl_merge(a0, a1, 16, lane);   // bit16: 0→a0, 1→a1
        float y = shfl_merge(a2, a3, 16, lane);   // bit16: 0→a2, 1→a3
        float z = shfl_merge(x,  y,  8,  lane);   // bit8:  0→x,  1→y
        z += __shfl_xor_sync(0xffffffffu, z, 4);
        z += __shfl_xor_sync(0xffffffffu, z, 2);
        z += __shfl_xor_sync(0xffffffffu, z, 1);

        if (writer)
          out[(size_t)(b * T + r) * L + 4 * g + idx] = z + bias;

        if (g == 0) {  // relay for t = r
          float rel = 0.f;
#pragma unroll
          for (int j = 0; j < 8; j++)
            rel = fmaf(fmaxf(cur.v[j], nxt.v[j]), rw[j], rel);
#pragma unroll
          for (int s = 16; s > 0; s >>= 1)
            rel += __shfl_xor_sync(0xffffffffu, rel, s);
          if (lane == 0) relay_out[(size_t)b * T + r] = rel + rb;
        }
      }
    }
  };

  // Interior strips touch rows [s0-19, s0+S-1+L] ⊂ [0, T): skip bounds checks.
  const bool interior = (s0 >= 20) && (s0 + S + L <= T);
  if (interior) body(FalseT{});
  else          body(TrueT{});
}

}  // namespace

extern "C" void kernel_launch(void* const* d_in, const int* in_sizes, int n_in,
                              void* d_out, int out_size) {
  const float* logits  = (const float*)d_in[0];
  const float* end_w   = (const float*)d_in[1];
  const float* whole_w = (const float*)d_in[2];
  const float* relay_w = (const float*)d_in[3];
  const float* relay_b = (const float*)d_in[4];
  const float* lbias   = (const float*)d_in[5];

  float* out   = (float*)d_out;                // [B, T, L]
  float* relay = out + (size_t)B * T * L;      // [B, T] appended

  ffm_kernel<<<NBLOCKS, THREADS>>>(logits, end_w, whole_w, relay_w, relay_b,
                                   lbias, out, relay);
}